// round 14
// baseline (speedup 1.0000x reference)
#include <cuda_runtime.h>
#include <cuda_fp16.h>
#include <math.h>
#include <stdint.h>

#define N_NODES 50000
#define DIM     128
#define NTM     391
#define MPAD    (NTM * 128)   // 50048, zero-padded rows
#define E_MAX   800000

// smem geometry for BK=64 tiles: 128 rows x 144B (128B payload + 16B pad)
#define TROW   144
#define TBYTES (128 * TROW)        // 18432
#define SMEM_MMA (4 * TBYTES)      // A0,W0,A1,W1 = 73728

// ---------------- fp32 scratch ---------------------------------------------------
__device__ __align__(16) float g_z    [2][N_NODES * DIM];
__device__ __align__(16) float g_cx   [2][N_NODES * DIM];
__device__ float g_bias [2][3][DIM];
__device__ float g_bias5[2][DIM];

// ---------------- CSR structures ---------------------------------------------------
__device__ int g_degi[2][N_NODES];
__device__ int g_off [2][N_NODES];
__device__ int g_cur [2][N_NODES];   // scan seeds this; fill bumps it
__device__ int g_srcs[2][E_MAX];

// ---------------- fp16 operands, row-major [MPAD][128] ------------------------------
__device__ __align__(16) __half g_Abf[2][4][(size_t)MPAD * DIM];  // 0=aggx 1=x 2=aggh 3=h
__device__ __align__(16) __half g_Bbf[2][2][(size_t)MPAD * DIM];  // 0=agghr 1=hr
__device__ __align__(16) __half g_W2A[2][3][128 * 512];
__device__ __align__(16) __half g_W2B[2][128 * 256];

// ---------------- helpers ----------------------------------------------------------
__device__ __forceinline__ uint32_t smem_u32(const void* p) {
    uint32_t a;
    asm("{ .reg .u64 t; cvta.to.shared.u64 t, %1; cvt.u32.u64 %0, t; }" : "=r"(a) : "l"(p));
    return a;
}
__device__ __forceinline__ void ldsm4(uint32_t* r, uint32_t addr) {
    asm volatile("ldmatrix.sync.aligned.m8n8.x4.shared.b16 {%0,%1,%2,%3}, [%4];"
                 : "=r"(r[0]), "=r"(r[1]), "=r"(r[2]), "=r"(r[3]) : "r"(addr));
}
__device__ __forceinline__ void mma16816(float* c, const uint32_t* a, uint32_t b0, uint32_t b1) {
    asm volatile(
        "mma.sync.aligned.m16n8k16.row.col.f32.f16.f16.f32 "
        "{%0,%1,%2,%3}, {%4,%5,%6,%7}, {%8,%9}, {%0,%1,%2,%3};"
        : "+f"(c[0]), "+f"(c[1]), "+f"(c[2]), "+f"(c[3])
        : "r"(a[0]), "r"(a[1]), "r"(a[2]), "r"(a[3]), "r"(b0), "r"(b1));
}
__device__ __forceinline__ float sigmoidf_(float v) { return 1.f / (1.f + expf(-v)); }
__device__ __forceinline__ uint32_t packh2(float x, float y) {
    __half2 v = __floats2half2_rn(x, y);
    return *(uint32_t*)&v;
}
__device__ __forceinline__ void h_store4(const float* v, void* dp) {
    *(uint2*)dp = make_uint2(packh2(v[0], v[1]), packh2(v[2], v[3]));
}
__device__ __forceinline__ void acc_h4(float* a, uint2 u) {
    float2 f0 = __half22float2(*(__half2*)&u.x);
    float2 f1 = __half22float2(*(__half2*)&u.y);
    a[0] += f0.x; a[1] += f0.y; a[2] += f1.x; a[3] += f1.y;
}
__device__ __forceinline__ uint4 packh8(const float* v) {
    return make_uint4(packh2(v[0], v[1]), packh2(v[2], v[3]),
                      packh2(v[4], v[5]), packh2(v[6], v[7]));
}

// ---------------- CSR build ---------------------------------------------------------
__global__ void k_zero2() {
    int i = blockIdx.x * blockDim.x + threadIdx.x;
    if (i < N_NODES) { g_degi[0][i] = 0; g_degi[1][i] = 0; }
}

__global__ void k_deg2(const int* __restrict__ dst_un, const int* __restrict__ dst_nu, int E) {
    int e = blockIdx.x * blockDim.x + threadIdx.x;
    if (e < E) {
        atomicAdd(&g_degi[1][dst_un[e]], 1);
        atomicAdd(&g_degi[0][dst_nu[e]], 1);
    }
}

__global__ void __launch_bounds__(1024) k_scan() {
    const int t = blockIdx.x;
    __shared__ int wsum[32];
    __shared__ int carry;
    if (threadIdx.x == 0) carry = 0;
    __syncthreads();
    int lane = threadIdx.x & 31, wid = threadIdx.x >> 5;
    for (int base = 0; base < N_NODES; base += 1024) {
        int i = base + threadIdx.x;
        int v = (i < N_NODES) ? g_degi[t][i] : 0;
        int s = v;
#pragma unroll
        for (int o = 1; o < 32; o <<= 1) {
            int u = __shfl_up_sync(0xFFFFFFFFu, s, o);
            if (lane >= o) s += u;
        }
        if (lane == 31) wsum[wid] = s;
        __syncthreads();
        if (wid == 0) {
            int ws = wsum[lane];
#pragma unroll
            for (int o = 1; o < 32; o <<= 1) {
                int u = __shfl_up_sync(0xFFFFFFFFu, ws, o);
                if (lane >= o) ws += u;
            }
            wsum[lane] = ws;
        }
        __syncthreads();
        int excl = carry + (wid > 0 ? wsum[wid - 1] : 0) + s - v;
        if (i < N_NODES) { g_off[t][i] = excl; g_cur[t][i] = excl; }
        int total = wsum[31];
        __syncthreads();
        if (threadIdx.x == 0) carry += total;
        __syncthreads();
    }
}

__global__ void k_fill(const int* __restrict__ src_un, const int* __restrict__ dst_un,
                       const int* __restrict__ src_nu, const int* __restrict__ dst_nu, int E) {
    int e = blockIdx.x * blockDim.x + threadIdx.x;
    if (e >= E) return;
    int d1 = dst_un[e];
    int p1 = atomicAdd(&g_cur[1][d1], 1);
    g_srcs[1][p1] = src_un[e];
    int d0 = dst_nu[e];
    int p0 = atomicAdd(&g_cur[0][d0], 1);
    g_srcs[0][p0] = src_nu[e];
}

// ---------------- gather aggregation (round-8 proven shape) ---------------------------
template <int TYP>
__global__ void k_agg_xh() {
    int w = (blockIdx.x * blockDim.x + threadIdx.x) >> 5;
    int lane = threadIdx.x & 31;
    if (w >= MPAD) return;
    int n = 0, beg = 0;
    if (w < N_NODES) { n = g_degi[TYP][w]; beg = g_off[TYP][w]; }
    const int* sp = &g_srcs[TYP][beg];
    const __half* xs = g_Abf[1 - TYP][1];
    const __half* hs = g_Abf[1 - TYP][3];
    float ax[4] = {0.f, 0.f, 0.f, 0.f};
    float ah[4] = {0.f, 0.f, 0.f, 0.f};
    int co = lane * 4;
    int j = 0;
    for (; j + 4 <= n; j += 4) {
        int s0 = __ldg(sp + j), s1 = __ldg(sp + j + 1);
        int s2 = __ldg(sp + j + 2), s3 = __ldg(sp + j + 3);
        uint2 x0 = *(const uint2*)(xs + (size_t)s0 * DIM + co);
        uint2 x1 = *(const uint2*)(xs + (size_t)s1 * DIM + co);
        uint2 x2 = *(const uint2*)(xs + (size_t)s2 * DIM + co);
        uint2 x3 = *(const uint2*)(xs + (size_t)s3 * DIM + co);
        uint2 h0 = *(const uint2*)(hs + (size_t)s0 * DIM + co);
        uint2 h1 = *(const uint2*)(hs + (size_t)s1 * DIM + co);
        uint2 h2 = *(const uint2*)(hs + (size_t)s2 * DIM + co);
        uint2 h3 = *(const uint2*)(hs + (size_t)s3 * DIM + co);
        acc_h4(ax, x0); acc_h4(ax, x1); acc_h4(ax, x2); acc_h4(ax, x3);
        acc_h4(ah, h0); acc_h4(ah, h1); acc_h4(ah, h2); acc_h4(ah, h3);
    }
    for (; j < n; j++) {
        int s = __ldg(sp + j);
        uint2 x0 = *(const uint2*)(xs + (size_t)s * DIM + co);
        uint2 h0 = *(const uint2*)(hs + (size_t)s * DIM + co);
        acc_h4(ax, x0); acc_h4(ah, h0);
    }
    float inv = 1.f / (float)max(n, 1);
#pragma unroll
    for (int i = 0; i < 4; i++) { ax[i] *= inv; ah[i] *= inv; }
    size_t off = (size_t)w * DIM + co;
    h_store4(ax, &g_Abf[TYP][0][off]);
    h_store4(ah, &g_Abf[TYP][2][off]);
}

template <int TYP>
__global__ void k_agg_hr() {
    int w = (blockIdx.x * blockDim.x + threadIdx.x) >> 5;
    int lane = threadIdx.x & 31;
    if (w >= MPAD) return;
    int n = 0, beg = 0;
    if (w < N_NODES) { n = g_degi[TYP][w]; beg = g_off[TYP][w]; }
    const int* sp = &g_srcs[TYP][beg];
    const __half* fs = g_Bbf[1 - TYP][1];
    float a[4] = {0.f, 0.f, 0.f, 0.f};
    int co = lane * 4;
    int j = 0;
    for (; j + 4 <= n; j += 4) {
        int s0 = __ldg(sp + j), s1 = __ldg(sp + j + 1);
        int s2 = __ldg(sp + j + 2), s3 = __ldg(sp + j + 3);
        uint2 v0 = *(const uint2*)(fs + (size_t)s0 * DIM + co);
        uint2 v1 = *(const uint2*)(fs + (size_t)s1 * DIM + co);
        uint2 v2 = *(const uint2*)(fs + (size_t)s2 * DIM + co);
        uint2 v3 = *(const uint2*)(fs + (size_t)s3 * DIM + co);
        acc_h4(a, v0); acc_h4(a, v1); acc_h4(a, v2); acc_h4(a, v3);
    }
    for (; j < n; j++) {
        int s = __ldg(sp + j);
        uint2 v0 = *(const uint2*)(fs + (size_t)s * DIM + co);
        acc_h4(a, v0);
    }
    float inv = 1.f / (float)max(n, 1);
#pragma unroll
    for (int i = 0; i < 4; i++) a[i] *= inv;
    size_t off = (size_t)w * DIM + co;
    h_store4(a, &g_Bbf[TYP][0][off]);
}

// ---------------- x/h -> fp16 (GEMM self operands) ------------------------------------
__global__ void k_conv_xh(const float* __restrict__ xu, const float* __restrict__ hu,
                          const float* __restrict__ xn, const float* __restrict__ hn) {
    int idx = blockIdx.x * blockDim.x + threadIdx.x;
    if (idx >= 2 * 2 * MPAD * 16) return;
    int g = idx & 15;
    int rid = idx >> 4;
    int row = rid % MPAD;
    int rest = rid / MPAD;
    int which = rest & 1;   // 0: x -> o=1, 1: h -> o=3
    int t = rest >> 1;
    float v[8] = {0, 0, 0, 0, 0, 0, 0, 0};
    if (row < N_NODES) {
        const float* src = (t == 0) ? (which ? hu : xu) : (which ? hn : xn);
        const float* p = src + (size_t)row * DIM + g * 8;
        float4 a = ((const float4*)p)[0];
        float4 b4 = ((const float4*)p)[1];
        v[0] = a.x; v[1] = a.y; v[2] = a.z; v[3] = a.w;
        v[4] = b4.x; v[5] = b4.y; v[6] = b4.z; v[7] = b4.w;
    }
    int o = which ? 3 : 1;
    size_t off = (size_t)row * DIM + g * 8;
    *(uint4*)&g_Abf[t][o][off] = packh8(v);
}

// ---------------- weight / bias repack (round-8 split form) ----------------------------
#define W2A_TOT (2 * 3 * 128 * 512)
#define W2B_TOT (2 * 128 * 256)
__global__ void k_repackW(const float* __restrict__ Wl, const float* __restrict__ Wr) {
    int idx = blockIdx.x * blockDim.x + threadIdx.x;
    if (idx < W2A_TOT) {
        int t = idx / (3 * 128 * 512);
        int r = idx % (3 * 128 * 512);
        int ct = r / (128 * 512);
        int r2 = r % (128 * 512);
        int n = r2 / 512;
        int k = r2 % 512;
        float w = 0.f;
        if (!(ct == 2 && k >= 256)) {
            int o = k >> 7, kk = k & 127;
            int gate = ct * 2 + ((o >= 2) ? 1 : 0);
            const float* Wsrc = ((o & 1) == 0) ? Wl : Wr;
            int wi = 1 - t;
            w = Wsrc[((size_t)(gate * 2 + wi) * 128 + kk) * 128 + n];
        }
        g_W2A[t][ct][n * 512 + k] = __float2half_rn(w);
        return;
    }
    int i2 = idx - W2A_TOT;
    if (i2 < W2B_TOT) {
        int t = i2 / (128 * 256);
        int r2 = i2 % (128 * 256);
        int n = r2 / 256;
        int k = r2 % 256;
        int o = k >> 7, kk = k & 127;
        const float* Wsrc = (o == 0) ? Wl : Wr;
        int wi = 1 - t;
        float w = Wsrc[((size_t)(5 * 2 + wi) * 128 + kk) * 128 + n];
        g_W2B[t][n * 256 + k] = __float2half_rn(w);
    }
}

__global__ void k_repack2(const float* __restrict__ b) {
    int idx = blockIdx.x * blockDim.x + threadIdx.x;
    if (idx >= 2 * 128) return;
    int t = idx / 128, c = idx % 128;
    int wi = 1 - t;
    g_bias[t][0][c] = b[(0 * 2 + wi) * 128 + c] + b[(1 * 2 + wi) * 128 + c];
    g_bias[t][1][c] = b[(2 * 2 + wi) * 128 + c] + b[(3 * 2 + wi) * 128 + c];
    g_bias[t][2][c] = b[(4 * 2 + wi) * 128 + c];
    g_bias5[t][c]   = b[(5 * 2 + wi) * 128 + c];
}

// ---------------- fp16 tensor-core GEMM, BK=64 (144B smem rows) ------------------------
__device__ __forceinline__ void load_tile64(uint32_t sa, uint32_t sw,
                                            const __half* Ag, const __half* Wg,
                                            int ldw, int tid) {
#pragma unroll
    for (int i = 0; i < 4; i++) {
        int c = tid * 4 + i;            // 0..1023: 128 rows x 8 chunks of 16B
        int row = c >> 3, q = c & 7;
        uint32_t d = sa + (uint32_t)(row * TROW + q * 16);
        const void* s = Ag + (size_t)row * 128 + q * 8;
        asm volatile("cp.async.cg.shared.global [%0], [%1], 16;" :: "r"(d), "l"(s));
        uint32_t d2 = sw + (uint32_t)(row * TROW + q * 16);
        const void* s2 = Wg + (size_t)row * ldw + q * 8;
        asm volatile("cp.async.cg.shared.global [%0], [%1], 16;" :: "r"(d2), "l"(s2));
    }
    asm volatile("cp.async.commit_group;");
}

template <int PASS>
__global__ void __launch_bounds__(256, 2) k_mma(const float* __restrict__ hu,
                                                const float* __restrict__ hn,
                                                float* __restrict__ out) {
    extern __shared__ __align__(16) unsigned char smraw[];
    const int typ = blockIdx.z, ct = blockIdx.y, tm = blockIdx.x;
    const int tid = threadIdx.x, wid = tid >> 5, lane = tid & 31;
    const int wm = wid & 1, wn = wid >> 1;

    const int NO   = (PASS == 0) ? ((ct < 2) ? 4 : 2) : 2;
    const int NIT  = NO * 2;                 // BK=64 -> 2 iters per 128-K operand
    const int ldw  = (PASS == 0) ? 512 : 256;
    const __half* Wrow = (PASS == 0) ? g_W2A[typ][ct] : g_W2B[typ];

    uint32_t base = smem_u32(smraw);
    uint32_t sAu[2] = { base,               base + 2 * TBYTES };
    uint32_t sWu[2] = { base + TBYTES,      base + 3 * TBYTES };

    float acc[4][4][4];
#pragma unroll
    for (int a = 0; a < 4; a++)
#pragma unroll
        for (int bq = 0; bq < 4; bq++)
#pragma unroll
            for (int cq = 0; cq < 4; cq++) acc[a][bq][cq] = 0.f;

    auto asegp = [&](int s) -> const __half* {
        return (PASS == 0) ? &g_Abf[typ][s][0] : &g_Bbf[typ][s][0];
    };

    {
        const __half* Ag = asegp(0) + (size_t)(tm * 128) * 128;
        load_tile64(sAu[0], sWu[0], Ag, Wrow, ldw, tid);
    }

#pragma unroll 1
    for (int kt = 0; kt < NIT; kt++) {
        int bsel = kt & 1;
        if (kt + 1 < NIT) {
            int s = (kt + 1) >> 1, kk = ((kt + 1) & 1) * 64;
            const __half* Ag = asegp(s) + (size_t)(tm * 128) * 128 + kk;
            const __half* Wg = Wrow + s * 128 + kk;
            load_tile64(sAu[bsel ^ 1], sWu[bsel ^ 1], Ag, Wg, ldw, tid);
            asm volatile("cp.async.wait_group 1;");
        } else {
            asm volatile("cp.async.wait_group 0;");
        }
        __syncthreads();

        uint32_t aB = sAu[bsel] + (uint32_t)((wm * 64) * TROW);
        uint32_t bB = sWu[bsel] + (uint32_t)((wn * 32) * TROW);
#pragma unroll
        for (int k16 = 0; k16 < 4; k16++) {
            uint32_t afr[4][4], bfr[2][4];
#pragma unroll
            for (int mt = 0; mt < 4; mt++) {
                uint32_t addr = aB + (uint32_t)((mt * 16 + (lane & 15)) * TROW +
                                                k16 * 32 + (lane >> 4) * 16);
                ldsm4(afr[mt], addr);
            }
#pragma unroll
            for (int np = 0; np < 2; np++) {
                uint32_t addr = bB + (uint32_t)((np * 16 + (lane & 7) + ((lane >> 4) * 8)) * TROW +
                                                k16 * 32 + ((lane >> 3) & 1) * 16);
                ldsm4(bfr[np], addr);
            }
#pragma unroll
            for (int mt = 0; mt < 4; mt++)
#pragma unroll
                for (int nt = 0; nt < 4; nt++)
                    mma16816(acc[mt][nt], afr[mt],
                             bfr[nt >> 1][(nt & 1) * 2], bfr[nt >> 1][(nt & 1) * 2 + 1]);
        }
        __syncthreads();
    }

    // ---------------- epilogue ----------------
    const float* hself = typ ? hn : hu;
    int rowW = tm * 128 + wm * 64;
    int colW = wn * 32;
#pragma unroll
    for (int mt = 0; mt < 4; mt++) {
#pragma unroll
        for (int i = 0; i < 2; i++) {
            int row = rowW + mt * 16 + (lane >> 2) + i * 8;
            if (row >= N_NODES) continue;
#pragma unroll
            for (int nt = 0; nt < 4; nt++) {
                int col = colW + nt * 8 + (lane & 3) * 2;
                size_t off = (size_t)row * DIM + col;
                float v0, v1;
                if (PASS == 0) {
                    const float* bias = g_bias[typ][ct];
                    v0 = acc[mt][nt][i * 2 + 0] + bias[col];
                    v1 = acc[mt][nt][i * 2 + 1] + bias[col + 1];
                    if (ct == 0) {
                        *(float2*)&g_z[typ][off] = make_float2(sigmoidf_(v0), sigmoidf_(v1));
                    } else if (ct == 1) {
                        float2 h2 = *(const float2*)&hself[off];
                        float hr0 = h2.x * sigmoidf_(v0);
                        float hr1 = h2.y * sigmoidf_(v1);
                        *(uint32_t*)&g_Bbf[typ][1][off] = packh2(hr0, hr1);
                    } else {
                        *(float2*)&g_cx[typ][off] = make_float2(v0, v1);
                    }
                } else {
                    const float* bias = g_bias5[typ];
                    v0 = acc[mt][nt][i * 2 + 0] + bias[col];
                    v1 = acc[mt][nt][i * 2 + 1] + bias[col + 1];
                    float2 cx2 = *(const float2*)&g_cx[typ][off];
                    float2 z2  = *(const float2*)&g_z[typ][off];
                    float2 h2  = *(const float2*)&hself[off];
                    float ht0 = tanhf(cx2.x + v0);
                    float ht1 = tanhf(cx2.y + v1);
                    float2 o2;
                    o2.x = z2.x * h2.x + (1.f - z2.x) * ht0;
                    o2.y = z2.y * h2.y + (1.f - z2.y) * ht1;
                    *(float2*)&out[(size_t)typ * N_NODES * DIM + off] = o2;
                }
            }
        }
    }
}

// ---------------- launch ----------------------------------------------------------------
extern "C" void kernel_launch(void* const* d_in, const int* in_sizes, int n_in,
                              void* d_out, int out_size) {
    const float* x_user = (const float*)d_in[0];
    const float* x_news = (const float*)d_in[1];
    const float* h_user = (const float*)d_in[2];
    const float* h_news = (const float*)d_in[3];
    const float* Wl     = (const float*)d_in[4];
    const float* Wr     = (const float*)d_in[5];
    const float* b      = (const float*)d_in[6];
    const int* src_un   = (const int*)d_in[7];
    const int* dst_un   = (const int*)d_in[8];
    const int* src_nu   = (const int*)d_in[9];
    const int* dst_nu   = (const int*)d_in[10];
    float* out = (float*)d_out;
    const int E = in_sizes[7];

    // opt-in dynamic smem (idempotent host-side calls, capture-safe)
    cudaFuncSetAttribute(k_mma<0>, cudaFuncAttributeMaxDynamicSharedMemorySize, SMEM_MMA);
    cudaFuncSetAttribute(k_mma<1>, cudaFuncAttributeMaxDynamicSharedMemorySize, SMEM_MMA);

    // CSR build
    k_zero2<<<(N_NODES + 255) / 256, 256>>>();
    k_deg2<<<(E + 255) / 256, 256>>>(dst_un, dst_nu, E);
    k_scan<<<2, 1024>>>();
    k_fill<<<(E + 255) / 256, 256>>>(src_un, dst_un, src_nu, dst_nu, E);

    // weight/bias prep + self-feature conversion
    k_repackW<<<(W2A_TOT + W2B_TOT + 255) / 256, 256>>>(Wl, Wr);
    k_repack2<<<1, 256>>>(b);
    k_conv_xh<<<(2 * 2 * MPAD * 16 + 255) / 256, 256>>>(x_user, h_user, x_news, h_news);

    // aggregation from fp16 tables (round-8 proven shape)
    int ablocks = (MPAD * 32 + 255) / 256;
    k_agg_xh<0><<<ablocks, 256>>>();
    k_agg_xh<1><<<ablocks, 256>>>();

    dim3 gA(NTM, 3, 2);
    k_mma<0><<<gA, 256, SMEM_MMA>>>(h_user, h_news, out);

    k_agg_hr<0><<<ablocks, 256>>>();
    k_agg_hr<1><<<ablocks, 256>>>();

    dim3 gB(NTM, 1, 2);
    k_mma<1><<<gB, 256, SMEM_MMA>>>(h_user, h_news, out);
}

// round 15
// speedup vs baseline: 1.0228x; 1.0228x over previous
#include <cuda_runtime.h>
#include <cuda_fp16.h>
#include <math.h>
#include <stdint.h>

#define N_NODES 50000
#define DIM     128
#define NTM     391
#define MPAD    (NTM * 128)   // 50048, zero-padded rows
#define E_MAX   800000

// ---------------- fp16 intermediate scratch (z, cx) --------------------------------
__device__ __align__(16) __half g_z [2][N_NODES * DIM];
__device__ __align__(16) __half g_cx[2][N_NODES * DIM];
__device__ float g_bias [2][3][DIM];
__device__ float g_bias5[2][DIM];

// ---------------- CSR structures ---------------------------------------------------
__device__ int g_degi[2][N_NODES];
__device__ int g_off [2][N_NODES];
__device__ int g_cur [2][N_NODES];   // scan seeds this; fill bumps it
__device__ int g_srcs[2][E_MAX];

// ---------------- fp16 operands, row-major [MPAD][128] ------------------------------
// A operands o: 0=aggx 1=x 2=aggh 3=h
__device__ __align__(16) __half g_Abf[2][4][(size_t)MPAD * DIM];
// B-pass operands o: 0=agghr 1=hr
__device__ __align__(16) __half g_Bbf[2][2][(size_t)MPAD * DIM];
// packed weights W^T: [n rows 128][k cols]; pass A K=512 (ct=2 uses first 256), pass B K=256
__device__ __align__(16) __half g_W2A[2][3][128 * 512];
__device__ __align__(16) __half g_W2B[2][128 * 256];

// ---------------- helpers ----------------------------------------------------------
__device__ __forceinline__ uint32_t smem_u32(const void* p) {
    uint32_t a;
    asm("{ .reg .u64 t; cvta.to.shared.u64 t, %1; cvt.u32.u64 %0, t; }" : "=r"(a) : "l"(p));
    return a;
}
__device__ __forceinline__ void ldsm4(uint32_t* r, uint32_t addr) {
    asm volatile("ldmatrix.sync.aligned.m8n8.x4.shared.b16 {%0,%1,%2,%3}, [%4];"
                 : "=r"(r[0]), "=r"(r[1]), "=r"(r[2]), "=r"(r[3]) : "r"(addr));
}
__device__ __forceinline__ void mma16816(float* c, const uint32_t* a, uint32_t b0, uint32_t b1) {
    asm volatile(
        "mma.sync.aligned.m16n8k16.row.col.f32.f16.f16.f32 "
        "{%0,%1,%2,%3}, {%4,%5,%6,%7}, {%8,%9}, {%0,%1,%2,%3};"
        : "+f"(c[0]), "+f"(c[1]), "+f"(c[2]), "+f"(c[3])
        : "r"(a[0]), "r"(a[1]), "r"(a[2]), "r"(a[3]), "r"(b0), "r"(b1));
}
__device__ __forceinline__ float sigmoidf_(float v) { return 1.f / (1.f + expf(-v)); }
__device__ __forceinline__ uint32_t packh2(float x, float y) {
    __half2 v = __floats2half2_rn(x, y);
    return *(uint32_t*)&v;
}
__device__ __forceinline__ float2 unpackh2(uint32_t u) {
    return __half22float2(*(__half2*)&u);
}
__device__ __forceinline__ void h_store4(const float* v, void* dp) {
    *(uint2*)dp = make_uint2(packh2(v[0], v[1]), packh2(v[2], v[3]));
}
__device__ __forceinline__ void acc_h4(float* a, uint2 u) {
    float2 f0 = __half22float2(*(__half2*)&u.x);
    float2 f1 = __half22float2(*(__half2*)&u.y);
    a[0] += f0.x; a[1] += f0.y; a[2] += f1.x; a[3] += f1.y;
}
__device__ __forceinline__ uint4 packh8(const float* v) {
    return make_uint4(packh2(v[0], v[1]), packh2(v[2], v[3]),
                      packh2(v[4], v[5]), packh2(v[6], v[7]));
}

// ---------------- CSR build ---------------------------------------------------------
__global__ void k_zero2() {
    int i = blockIdx.x * blockDim.x + threadIdx.x;
    if (i < N_NODES) { g_degi[0][i] = 0; g_degi[1][i] = 0; }
}

__global__ void k_deg2(const int* __restrict__ dst_un, const int* __restrict__ dst_nu, int E) {
    int e = blockIdx.x * blockDim.x + threadIdx.x;
    if (e < E) {
        atomicAdd(&g_degi[1][dst_un[e]], 1);
        atomicAdd(&g_degi[0][dst_nu[e]], 1);
    }
}

// one block per type; exclusive scan of degi -> off AND cur
__global__ void __launch_bounds__(1024) k_scan() {
    const int t = blockIdx.x;
    __shared__ int wsum[32];
    __shared__ int carry;
    if (threadIdx.x == 0) carry = 0;
    __syncthreads();
    int lane = threadIdx.x & 31, wid = threadIdx.x >> 5;
    for (int base = 0; base < N_NODES; base += 1024) {
        int i = base + threadIdx.x;
        int v = (i < N_NODES) ? g_degi[t][i] : 0;
        int s = v;
#pragma unroll
        for (int o = 1; o < 32; o <<= 1) {
            int u = __shfl_up_sync(0xFFFFFFFFu, s, o);
            if (lane >= o) s += u;
        }
        if (lane == 31) wsum[wid] = s;
        __syncthreads();
        if (wid == 0) {
            int ws = wsum[lane];
#pragma unroll
            for (int o = 1; o < 32; o <<= 1) {
                int u = __shfl_up_sync(0xFFFFFFFFu, ws, o);
                if (lane >= o) ws += u;
            }
            wsum[lane] = ws;
        }
        __syncthreads();
        int excl = carry + (wid > 0 ? wsum[wid - 1] : 0) + s - v;
        if (i < N_NODES) { g_off[t][i] = excl; g_cur[t][i] = excl; }
        int total = wsum[31];
        __syncthreads();
        if (threadIdx.x == 0) carry += total;
        __syncthreads();
    }
}

// slot comes straight from atomicAdd on cur (verified faster: 24.5 vs 25.9 us)
__global__ void k_fill(const int* __restrict__ src_un, const int* __restrict__ dst_un,
                       const int* __restrict__ src_nu, const int* __restrict__ dst_nu, int E) {
    int e = blockIdx.x * blockDim.x + threadIdx.x;
    if (e >= E) return;
    int d1 = dst_un[e];
    int p1 = atomicAdd(&g_cur[1][d1], 1);
    g_srcs[1][p1] = src_un[e];
    int d0 = dst_nu[e];
    int p0 = atomicAdd(&g_cur[0][d0], 1);
    g_srcs[0][p0] = src_nu[e];
}

// ---------------- gather aggregation (round-8 proven shape) ---------------------------
template <int TYP>
__global__ void k_agg_xh() {
    int w = (blockIdx.x * blockDim.x + threadIdx.x) >> 5;
    int lane = threadIdx.x & 31;
    if (w >= MPAD) return;
    int n = 0, beg = 0;
    if (w < N_NODES) { n = g_degi[TYP][w]; beg = g_off[TYP][w]; }
    const int* sp = &g_srcs[TYP][beg];
    const __half* xs = g_Abf[1 - TYP][1];
    const __half* hs = g_Abf[1 - TYP][3];
    float ax[4] = {0.f, 0.f, 0.f, 0.f};
    float ah[4] = {0.f, 0.f, 0.f, 0.f};
    int co = lane * 4;
    int j = 0;
    for (; j + 4 <= n; j += 4) {
        int s0 = __ldg(sp + j), s1 = __ldg(sp + j + 1);
        int s2 = __ldg(sp + j + 2), s3 = __ldg(sp + j + 3);
        uint2 x0 = *(const uint2*)(xs + (size_t)s0 * DIM + co);
        uint2 x1 = *(const uint2*)(xs + (size_t)s1 * DIM + co);
        uint2 x2 = *(const uint2*)(xs + (size_t)s2 * DIM + co);
        uint2 x3 = *(const uint2*)(xs + (size_t)s3 * DIM + co);
        uint2 h0 = *(const uint2*)(hs + (size_t)s0 * DIM + co);
        uint2 h1 = *(const uint2*)(hs + (size_t)s1 * DIM + co);
        uint2 h2 = *(const uint2*)(hs + (size_t)s2 * DIM + co);
        uint2 h3 = *(const uint2*)(hs + (size_t)s3 * DIM + co);
        acc_h4(ax, x0); acc_h4(ax, x1); acc_h4(ax, x2); acc_h4(ax, x3);
        acc_h4(ah, h0); acc_h4(ah, h1); acc_h4(ah, h2); acc_h4(ah, h3);
    }
    for (; j < n; j++) {
        int s = __ldg(sp + j);
        uint2 x0 = *(const uint2*)(xs + (size_t)s * DIM + co);
        uint2 h0 = *(const uint2*)(hs + (size_t)s * DIM + co);
        acc_h4(ax, x0); acc_h4(ah, h0);
    }
    float inv = 1.f / (float)max(n, 1);
#pragma unroll
    for (int i = 0; i < 4; i++) { ax[i] *= inv; ah[i] *= inv; }
    size_t off = (size_t)w * DIM + co;
    h_store4(ax, &g_Abf[TYP][0][off]);
    h_store4(ah, &g_Abf[TYP][2][off]);
}

template <int TYP>
__global__ void k_agg_hr() {
    int w = (blockIdx.x * blockDim.x + threadIdx.x) >> 5;
    int lane = threadIdx.x & 31;
    if (w >= MPAD) return;
    int n = 0, beg = 0;
    if (w < N_NODES) { n = g_degi[TYP][w]; beg = g_off[TYP][w]; }
    const int* sp = &g_srcs[TYP][beg];
    const __half* fs = g_Bbf[1 - TYP][1];
    float a[4] = {0.f, 0.f, 0.f, 0.f};
    int co = lane * 4;
    int j = 0;
    for (; j + 4 <= n; j += 4) {
        int s0 = __ldg(sp + j), s1 = __ldg(sp + j + 1);
        int s2 = __ldg(sp + j + 2), s3 = __ldg(sp + j + 3);
        uint2 v0 = *(const uint2*)(fs + (size_t)s0 * DIM + co);
        uint2 v1 = *(const uint2*)(fs + (size_t)s1 * DIM + co);
        uint2 v2 = *(const uint2*)(fs + (size_t)s2 * DIM + co);
        uint2 v3 = *(const uint2*)(fs + (size_t)s3 * DIM + co);
        acc_h4(a, v0); acc_h4(a, v1); acc_h4(a, v2); acc_h4(a, v3);
    }
    for (; j < n; j++) {
        int s = __ldg(sp + j);
        uint2 v0 = *(const uint2*)(fs + (size_t)s * DIM + co);
        acc_h4(a, v0);
    }
    float inv = 1.f / (float)max(n, 1);
#pragma unroll
    for (int i = 0; i < 4; i++) a[i] *= inv;
    size_t off = (size_t)w * DIM + co;
    h_store4(a, &g_Bbf[TYP][0][off]);
}

// ---------------- x/h -> fp16 (GEMM self operands) ------------------------------------
__global__ void k_conv_xh(const float* __restrict__ xu, const float* __restrict__ hu,
                          const float* __restrict__ xn, const float* __restrict__ hn) {
    int idx = blockIdx.x * blockDim.x + threadIdx.x;
    if (idx >= 2 * 2 * MPAD * 16) return;
    int g = idx & 15;
    int rid = idx >> 4;
    int row = rid % MPAD;
    int rest = rid / MPAD;
    int which = rest & 1;   // 0: x -> o=1, 1: h -> o=3
    int t = rest >> 1;
    float v[8] = {0, 0, 0, 0, 0, 0, 0, 0};
    if (row < N_NODES) {
        const float* src = (t == 0) ? (which ? hu : xu) : (which ? hn : xn);
        const float* p = src + (size_t)row * DIM + g * 8;
        float4 a = ((const float4*)p)[0];
        float4 b4 = ((const float4*)p)[1];
        v[0] = a.x; v[1] = a.y; v[2] = a.z; v[3] = a.w;
        v[4] = b4.x; v[5] = b4.y; v[6] = b4.z; v[7] = b4.w;
    }
    int o = which ? 3 : 1;
    size_t off = (size_t)row * DIM + g * 8;
    *(uint4*)&g_Abf[t][o][off] = packh8(v);
}

// ---------------- weight / bias repack (round-8 split form) ----------------------------
#define W2A_TOT (2 * 3 * 128 * 512)
#define W2B_TOT (2 * 128 * 256)
__global__ void k_repackW(const float* __restrict__ Wl, const float* __restrict__ Wr) {
    int idx = blockIdx.x * blockDim.x + threadIdx.x;
    if (idx < W2A_TOT) {
        int t = idx / (3 * 128 * 512);
        int r = idx % (3 * 128 * 512);
        int ct = r / (128 * 512);
        int r2 = r % (128 * 512);
        int n = r2 / 512;
        int k = r2 % 512;
        float w = 0.f;
        if (!(ct == 2 && k >= 256)) {
            int o = k >> 7, kk = k & 127;
            int gate = ct * 2 + ((o >= 2) ? 1 : 0);
            const float* Wsrc = ((o & 1) == 0) ? Wl : Wr;
            int wi = 1 - t;
            w = Wsrc[((size_t)(gate * 2 + wi) * 128 + kk) * 128 + n];
        }
        g_W2A[t][ct][n * 512 + k] = __float2half_rn(w);
        return;
    }
    int i2 = idx - W2A_TOT;
    if (i2 < W2B_TOT) {
        int t = i2 / (128 * 256);
        int r2 = i2 % (128 * 256);
        int n = r2 / 256;
        int k = r2 % 256;
        int o = k >> 7, kk = k & 127;
        const float* Wsrc = (o == 0) ? Wl : Wr;
        int wi = 1 - t;
        float w = Wsrc[((size_t)(5 * 2 + wi) * 128 + kk) * 128 + n];
        g_W2B[t][n * 256 + k] = __float2half_rn(w);
    }
}

__global__ void k_repack2(const float* __restrict__ b) {
    int idx = blockIdx.x * blockDim.x + threadIdx.x;
    if (idx >= 2 * 128) return;
    int t = idx / 128, c = idx % 128;
    int wi = 1 - t;
    g_bias[t][0][c] = b[(0 * 2 + wi) * 128 + c] + b[(1 * 2 + wi) * 128 + c];
    g_bias[t][1][c] = b[(2 * 2 + wi) * 128 + c] + b[(3 * 2 + wi) * 128 + c];
    g_bias[t][2][c] = b[(4 * 2 + wi) * 128 + c];
    g_bias5[t][c]   = b[(5 * 2 + wi) * 128 + c];
}

// ---------------- fp16 tensor-core GEMM (round-8 BK=32 form) ---------------------------
__device__ __forceinline__ void load_tile(uint32_t sa, uint32_t sw,
                                          const __half* Ag, const __half* Wg,
                                          int ldw, int tid) {
#pragma unroll
    for (int i = 0; i < 2; i++) {
        int c = tid * 2 + i;
        int row = c >> 2, q = c & 3;
        uint32_t d = sa + (uint32_t)(row * 80 + q * 16);
        const void* s = Ag + (size_t)row * 128 + q * 8;
        asm volatile("cp.async.cg.shared.global [%0], [%1], 16;" :: "r"(d), "l"(s));
        uint32_t d2 = sw + (uint32_t)(row * 80 + q * 16);
        const void* s2 = Wg + (size_t)row * ldw + q * 8;
        asm volatile("cp.async.cg.shared.global [%0], [%1], 16;" :: "r"(d2), "l"(s2));
    }
    asm volatile("cp.async.commit_group;");
}

template <int PASS>
__global__ void __launch_bounds__(256, 2) k_mma(const float* __restrict__ hu,
                                                const float* __restrict__ hn,
                                                float* __restrict__ out) {
    __shared__ __align__(16) unsigned char sA[2][128 * 80];
    __shared__ __align__(16) unsigned char sW[2][128 * 80];
    const int typ = blockIdx.z, ct = blockIdx.y, tm = blockIdx.x;
    const int tid = threadIdx.x, wid = tid >> 5, lane = tid & 31;
    const int wm = wid & 1, wn = wid >> 1;

    const int NO   = (PASS == 0) ? ((ct < 2) ? 4 : 2) : 2;
    const int NIT  = NO * 4;
    const int ldw  = (PASS == 0) ? 512 : 256;
    const __half* Wrow = (PASS == 0) ? g_W2A[typ][ct] : g_W2B[typ];

    uint32_t sAu[2] = { smem_u32(sA[0]), smem_u32(sA[1]) };
    uint32_t sWu[2] = { smem_u32(sW[0]), smem_u32(sW[1]) };

    float acc[4][4][4];
#pragma unroll
    for (int a = 0; a < 4; a++)
#pragma unroll
        for (int bq = 0; bq < 4; bq++)
#pragma unroll
            for (int cq = 0; cq < 4; cq++) acc[a][bq][cq] = 0.f;

    auto asegp = [&](int s) -> const __half* {
        return (PASS == 0) ? &g_Abf[typ][s][0] : &g_Bbf[typ][s][0];
    };

    {
        const __half* Ag = asegp(0) + (size_t)(tm * 128) * 128;
        load_tile(sAu[0], sWu[0], Ag, Wrow, ldw, tid);
    }

#pragma unroll 1
    for (int kt = 0; kt < NIT; kt++) {
        int bsel = kt & 1;
        if (kt + 1 < NIT) {
            int s = (kt + 1) >> 2, kk = ((kt + 1) & 3) * 32;
            const __half* Ag = asegp(s) + (size_t)(tm * 128) * 128 + kk;
            const __half* Wg = Wrow + s * 128 + kk;
            load_tile(sAu[bsel ^ 1], sWu[bsel ^ 1], Ag, Wg, ldw, tid);
            asm volatile("cp.async.wait_group 1;");
        } else {
            asm volatile("cp.async.wait_group 0;");
        }
        __syncthreads();

        uint32_t aB = sAu[bsel] + (uint32_t)((wm * 64) * 80);
        uint32_t bB = sWu[bsel] + (uint32_t)((wn * 32) * 80);
#pragma unroll
        for (int k16 = 0; k16 < 2; k16++) {
            uint32_t afr[4][4], bfr[2][4];
#pragma unroll
            for (int mt = 0; mt < 4; mt++) {
                uint32_t addr = aB + (uint32_t)((mt * 16 + (lane & 15)) * 80 +
                                                k16 * 32 + (lane >> 4) * 16);
                ldsm4(afr[mt], addr);
            }
#pragma unroll
            for (int np = 0; np < 2; np++) {
                uint32_t addr = bB + (uint32_t)((np * 16 + (lane & 7) + ((lane >> 4) * 8)) * 80 +
                                                k16 * 32 + ((lane >> 3) & 1) * 16);
                ldsm4(bfr[np], addr);
            }
#pragma unroll
            for (int mt = 0; mt < 4; mt++)
#pragma unroll
                for (int nt = 0; nt < 4; nt++)
                    mma16816(acc[mt][nt], afr[mt],
                             bfr[nt >> 1][(nt & 1) * 2], bfr[nt >> 1][(nt & 1) * 2 + 1]);
        }
        __syncthreads();
    }

    // ---------------- epilogue ----------------
    const float* hself = typ ? hn : hu;
    int rowW = tm * 128 + wm * 64;
    int colW = wn * 32;
#pragma unroll
    for (int mt = 0; mt < 4; mt++) {
#pragma unroll
        for (int i = 0; i < 2; i++) {
            int row = rowW + mt * 16 + (lane >> 2) + i * 8;
            if (row >= N_NODES) continue;
#pragma unroll
            for (int nt = 0; nt < 4; nt++) {
                int col = colW + nt * 8 + (lane & 3) * 2;
                size_t off = (size_t)row * DIM + col;
                float v0, v1;
                if (PASS == 0) {
                    const float* bias = g_bias[typ][ct];
                    v0 = acc[mt][nt][i * 2 + 0] + bias[col];
                    v1 = acc[mt][nt][i * 2 + 1] + bias[col + 1];
                    if (ct == 0) {
                        *(uint32_t*)&g_z[typ][off] = packh2(sigmoidf_(v0), sigmoidf_(v1));
                    } else if (ct == 1) {
                        float2 h2 = *(const float2*)&hself[off];
                        float hr0 = h2.x * sigmoidf_(v0);
                        float hr1 = h2.y * sigmoidf_(v1);
                        *(uint32_t*)&g_Bbf[typ][1][off] = packh2(hr0, hr1);
                    } else {
                        *(uint32_t*)&g_cx[typ][off] = packh2(v0, v1);
                    }
                } else {
                    const float* bias = g_bias5[typ];
                    v0 = acc[mt][nt][i * 2 + 0] + bias[col];
                    v1 = acc[mt][nt][i * 2 + 1] + bias[col + 1];
                    float2 cx2 = unpackh2(*(const uint32_t*)&g_cx[typ][off]);
                    float2 z2  = unpackh2(*(const uint32_t*)&g_z[typ][off]);
                    float2 h2  = *(const float2*)&hself[off];
                    float ht0 = tanhf(cx2.x + v0);
                    float ht1 = tanhf(cx2.y + v1);
                    float2 o2;
                    o2.x = z2.x * h2.x + (1.f - z2.x) * ht0;
                    o2.y = z2.y * h2.y + (1.f - z2.y) * ht1;
                    *(float2*)&out[(size_t)typ * N_NODES * DIM + off] = o2;
                }
            }
        }
    }
}

// ---------------- launch ----------------------------------------------------------------
extern "C" void kernel_launch(void* const* d_in, const int* in_sizes, int n_in,
                              void* d_out, int out_size) {
    const float* x_user = (const float*)d_in[0];
    const float* x_news = (const float*)d_in[1];
    const float* h_user = (const float*)d_in[2];
    const float* h_news = (const float*)d_in[3];
    const float* Wl     = (const float*)d_in[4];
    const float* Wr     = (const float*)d_in[5];
    const float* b      = (const float*)d_in[6];
    const int* src_un   = (const int*)d_in[7];
    const int* dst_un   = (const int*)d_in[8];
    const int* src_nu   = (const int*)d_in[9];
    const int* dst_nu   = (const int*)d_in[10];
    float* out = (float*)d_out;
    const int E = in_sizes[7];

    // CSR build
    k_zero2<<<(N_NODES + 255) / 256, 256>>>();
    k_deg2<<<(E + 255) / 256, 256>>>(dst_un, dst_nu, E);
    k_scan<<<2, 1024>>>();
    k_fill<<<(E + 255) / 256, 256>>>(src_un, dst_un, src_nu, dst_nu, E);

    // weight/bias prep + self-feature conversion
    k_repackW<<<(W2A_TOT + W2B_TOT + 255) / 256, 256>>>(Wl, Wr);
    k_repack2<<<1, 256>>>(b);
    k_conv_xh<<<(2 * 2 * MPAD * 16 + 255) / 256, 256>>>(x_user, h_user, x_news, h_news);

    // aggregation from fp16 tables (round-8 proven shape)
    int ablocks = (MPAD * 32 + 255) / 256;
    k_agg_xh<0><<<ablocks, 256>>>();   // user dst <- news fp16 x/h
    k_agg_xh<1><<<ablocks, 256>>>();   // news dst <- user fp16 x/h

    dim3 gA(NTM, 3, 2);
    k_mma<0><<<gA, 256>>>(h_user, h_news, out);

    k_agg_hr<0><<<ablocks, 256>>>();
    k_agg_hr<1><<<ablocks, 256>>>();

    dim3 gB(NTM, 1, 2);
    k_mma<1><<<gB, 256>>>(h_user, h_news, out);
}

// round 16
// speedup vs baseline: 1.0263x; 1.0034x over previous
#include <cuda_runtime.h>
#include <cuda_fp16.h>
#include <math.h>
#include <stdint.h>

#define N_NODES 50000
#define DIM     128
#define NTM     391
#define MPAD    (NTM * 128)   // 50048, zero-padded rows
#define E_MAX   800000

// ---------------- fp32 scratch ---------------------------------------------------
__device__ __align__(16) float g_z    [2][N_NODES * DIM];
__device__ __align__(16) float g_cx   [2][N_NODES * DIM];
__device__ float g_bias [2][3][DIM];
__device__ float g_bias5[2][DIM];

// ---------------- CSR structures ---------------------------------------------------
__device__ int g_degi[2][N_NODES];
__device__ int g_off [2][N_NODES];
__device__ int g_cur [2][N_NODES];
__device__ int g_srcs[2][E_MAX];

// ---------------- fp16 operands, row-major [MPAD][128] ------------------------------
// A operands o: 0=aggx 1=x 2=aggh 3=h
__device__ __align__(16) __half g_Abf[2][4][(size_t)MPAD * DIM];
// B-pass operands o: 0=agghr 1=hr
__device__ __align__(16) __half g_Bbf[2][2][(size_t)MPAD * DIM];
// packed weights W^T: [n rows 128][k cols]; pass A K=512 (ct=2 uses first 256), pass B K=256
__device__ __align__(16) __half g_W2A[2][3][128 * 512];
__device__ __align__(16) __half g_W2B[2][128 * 256];

// ---------------- helpers ----------------------------------------------------------
__device__ __forceinline__ uint32_t smem_u32(const void* p) {
    uint32_t a;
    asm("{ .reg .u64 t; cvta.to.shared.u64 t, %1; cvt.u32.u64 %0, t; }" : "=r"(a) : "l"(p));
    return a;
}
__device__ __forceinline__ void ldsm4(uint32_t* r, uint32_t addr) {
    asm volatile("ldmatrix.sync.aligned.m8n8.x4.shared.b16 {%0,%1,%2,%3}, [%4];"
                 : "=r"(r[0]), "=r"(r[1]), "=r"(r[2]), "=r"(r[3]) : "r"(addr));
}
__device__ __forceinline__ void mma16816(float* c, const uint32_t* a, uint32_t b0, uint32_t b1) {
    asm volatile(
        "mma.sync.aligned.m16n8k16.row.col.f32.f16.f16.f32 "
        "{%0,%1,%2,%3}, {%4,%5,%6,%7}, {%8,%9}, {%0,%1,%2,%3};"
        : "+f"(c[0]), "+f"(c[1]), "+f"(c[2]), "+f"(c[3])
        : "r"(a[0]), "r"(a[1]), "r"(a[2]), "r"(a[3]), "r"(b0), "r"(b1));
}
__device__ __forceinline__ float sigmoidf_(float v) { return 1.f / (1.f + expf(-v)); }
__device__ __forceinline__ uint32_t packh2(float x, float y) {
    __half2 v = __floats2half2_rn(x, y);
    return *(uint32_t*)&v;
}
__device__ __forceinline__ void h_store4(const float* v, void* dp) {
    *(uint2*)dp = make_uint2(packh2(v[0], v[1]), packh2(v[2], v[3]));
}
// accumulate uint2 (4 halves) into float[4]
__device__ __forceinline__ void acc_h4(float* a, uint2 u) {
    float2 f0 = __half22float2(*(__half2*)&u.x);
    float2 f1 = __half22float2(*(__half2*)&u.y);
    a[0] += f0.x; a[1] += f0.y; a[2] += f1.x; a[3] += f1.y;
}
__device__ __forceinline__ uint4 packh8(const float* v) {
    return make_uint4(packh2(v[0], v[1]), packh2(v[2], v[3]),
                      packh2(v[4], v[5]), packh2(v[6], v[7]));
}

// ---------------- CSR build ---------------------------------------------------------
__global__ void k_zero2() {
    int i = blockIdx.x * blockDim.x + threadIdx.x;
    if (i < N_NODES) {
        g_degi[0][i] = 0; g_degi[1][i] = 0;
        g_cur[0][i] = 0;  g_cur[1][i] = 0;
    }
}

__global__ void k_deg2(const int* __restrict__ dst_un, const int* __restrict__ dst_nu, int E) {
    int e = blockIdx.x * blockDim.x + threadIdx.x;
    if (e < E) {
        atomicAdd(&g_degi[1][dst_un[e]], 1);
        atomicAdd(&g_degi[0][dst_nu[e]], 1);
    }
}

// one block per type; exclusive scan of degi -> off
__global__ void __launch_bounds__(1024) k_scan() {
    const int t = blockIdx.x;
    __shared__ int wsum[32];
    __shared__ int carry;
    if (threadIdx.x == 0) carry = 0;
    __syncthreads();
    int lane = threadIdx.x & 31, wid = threadIdx.x >> 5;
    for (int base = 0; base < N_NODES; base += 1024) {
        int i = base + threadIdx.x;
        int v = (i < N_NODES) ? g_degi[t][i] : 0;
        int s = v;
#pragma unroll
        for (int o = 1; o < 32; o <<= 1) {
            int u = __shfl_up_sync(0xFFFFFFFFu, s, o);
            if (lane >= o) s += u;
        }
        if (lane == 31) wsum[wid] = s;
        __syncthreads();
        if (wid == 0) {
            int ws = wsum[lane];
#pragma unroll
            for (int o = 1; o < 32; o <<= 1) {
                int u = __shfl_up_sync(0xFFFFFFFFu, ws, o);
                if (lane >= o) ws += u;
            }
            wsum[lane] = ws;
        }
        __syncthreads();
        int excl = carry + (wid > 0 ? wsum[wid - 1] : 0) + s - v;
        if (i < N_NODES) g_off[t][i] = excl;
        int total = wsum[31];
        __syncthreads();
        if (threadIdx.x == 0) carry += total;
        __syncthreads();
    }
}

__global__ void k_fill(const int* __restrict__ src_un, const int* __restrict__ dst_un,
                       const int* __restrict__ src_nu, const int* __restrict__ dst_nu, int E) {
    int e = blockIdx.x * blockDim.x + threadIdx.x;
    if (e >= E) return;
    int d1 = dst_un[e];
    int p1 = atomicAdd(&g_cur[1][d1], 1);
    g_srcs[1][g_off[1][d1] + p1] = src_un[e];
    int d0 = dst_nu[e];
    int p0 = atomicAdd(&g_cur[0][d0], 1);
    g_srcs[0][g_off[0][d0] + p0] = src_nu[e];
}

// ---------------- gather aggregation from fp16 tables: warp per dst row ---------------
// source features: fp16 x/h of the OTHER node type (g_Abf[1-TYP][1], [3])
template <int TYP>
__global__ void k_agg_xh() {
    int w = (blockIdx.x * blockDim.x + threadIdx.x) >> 5;
    int lane = threadIdx.x & 31;
    if (w >= MPAD) return;
    int n = 0, beg = 0;
    if (w < N_NODES) { n = g_degi[TYP][w]; beg = g_off[TYP][w]; }
    const int* sp = &g_srcs[TYP][beg];
    const __half* xs = g_Abf[1 - TYP][1];
    const __half* hs = g_Abf[1 - TYP][3];
    float ax[4] = {0.f, 0.f, 0.f, 0.f};
    float ah[4] = {0.f, 0.f, 0.f, 0.f};
    int co = lane * 4;
    int j = 0;
    for (; j + 4 <= n; j += 4) {
        int s0 = __ldg(sp + j), s1 = __ldg(sp + j + 1);
        int s2 = __ldg(sp + j + 2), s3 = __ldg(sp + j + 3);
        uint2 x0 = *(const uint2*)(xs + (size_t)s0 * DIM + co);
        uint2 x1 = *(const uint2*)(xs + (size_t)s1 * DIM + co);
        uint2 x2 = *(const uint2*)(xs + (size_t)s2 * DIM + co);
        uint2 x3 = *(const uint2*)(xs + (size_t)s3 * DIM + co);
        uint2 h0 = *(const uint2*)(hs + (size_t)s0 * DIM + co);
        uint2 h1 = *(const uint2*)(hs + (size_t)s1 * DIM + co);
        uint2 h2 = *(const uint2*)(hs + (size_t)s2 * DIM + co);
        uint2 h3 = *(const uint2*)(hs + (size_t)s3 * DIM + co);
        acc_h4(ax, x0); acc_h4(ax, x1); acc_h4(ax, x2); acc_h4(ax, x3);
        acc_h4(ah, h0); acc_h4(ah, h1); acc_h4(ah, h2); acc_h4(ah, h3);
    }
    for (; j < n; j++) {
        int s = __ldg(sp + j);
        uint2 x0 = *(const uint2*)(xs + (size_t)s * DIM + co);
        uint2 h0 = *(const uint2*)(hs + (size_t)s * DIM + co);
        acc_h4(ax, x0); acc_h4(ah, h0);
    }
    float inv = 1.f / (float)max(n, 1);
#pragma unroll
    for (int i = 0; i < 4; i++) { ax[i] *= inv; ah[i] *= inv; }
    size_t off = (size_t)w * DIM + co;
    h_store4(ax, &g_Abf[TYP][0][off]);
    h_store4(ah, &g_Abf[TYP][2][off]);
}

// source features: fp16 hr of the OTHER node type (g_Bbf[1-TYP][1])
template <int TYP>
__global__ void k_agg_hr() {
    int w = (blockIdx.x * blockDim.x + threadIdx.x) >> 5;
    int lane = threadIdx.x & 31;
    if (w >= MPAD) return;
    int n = 0, beg = 0;
    if (w < N_NODES) { n = g_degi[TYP][w]; beg = g_off[TYP][w]; }
    const int* sp = &g_srcs[TYP][beg];
    const __half* fs = g_Bbf[1 - TYP][1];
    float a[4] = {0.f, 0.f, 0.f, 0.f};
    int co = lane * 4;
    int j = 0;
    for (; j + 4 <= n; j += 4) {
        int s0 = __ldg(sp + j), s1 = __ldg(sp + j + 1);
        int s2 = __ldg(sp + j + 2), s3 = __ldg(sp + j + 3);
        uint2 v0 = *(const uint2*)(fs + (size_t)s0 * DIM + co);
        uint2 v1 = *(const uint2*)(fs + (size_t)s1 * DIM + co);
        uint2 v2 = *(const uint2*)(fs + (size_t)s2 * DIM + co);
        uint2 v3 = *(const uint2*)(fs + (size_t)s3 * DIM + co);
        acc_h4(a, v0); acc_h4(a, v1); acc_h4(a, v2); acc_h4(a, v3);
    }
    for (; j < n; j++) {
        int s = __ldg(sp + j);
        uint2 v0 = *(const uint2*)(fs + (size_t)s * DIM + co);
        acc_h4(a, v0);
    }
    float inv = 1.f / (float)max(n, 1);
#pragma unroll
    for (int i = 0; i < 4; i++) a[i] *= inv;
    size_t off = (size_t)w * DIM + co;
    h_store4(a, &g_Bbf[TYP][0][off]);
}

// ---------------- x/h -> fp16 (GEMM self operands) ------------------------------------
__global__ void k_conv_xh(const float* __restrict__ xu, const float* __restrict__ hu,
                          const float* __restrict__ xn, const float* __restrict__ hn) {
    int idx = blockIdx.x * blockDim.x + threadIdx.x;
    if (idx >= 2 * 2 * MPAD * 16) return;
    int g = idx & 15;
    int rid = idx >> 4;
    int row = rid % MPAD;
    int rest = rid / MPAD;
    int which = rest & 1;   // 0: x -> o=1, 1: h -> o=3
    int t = rest >> 1;
    float v[8] = {0, 0, 0, 0, 0, 0, 0, 0};
    if (row < N_NODES) {
        const float* src = (t == 0) ? (which ? hu : xu) : (which ? hn : xn);
        const float* p = src + (size_t)row * DIM + g * 8;
        float4 a = ((const float4*)p)[0];
        float4 b4 = ((const float4*)p)[1];
        v[0] = a.x; v[1] = a.y; v[2] = a.z; v[3] = a.w;
        v[4] = b4.x; v[5] = b4.y; v[6] = b4.z; v[7] = b4.w;
    }
    int o = which ? 3 : 1;
    size_t off = (size_t)row * DIM + g * 8;
    uint4 pk = packh8(v);
    *(uint4*)&g_Abf[t][o][off] = pk;
}

// ---------------- weight / bias repack ----------------------------------------------
#define W2A_TOT (2 * 3 * 128 * 512)
#define W2B_TOT (2 * 128 * 256)
__global__ void k_repackW(const float* __restrict__ Wl, const float* __restrict__ Wr) {
    int idx = blockIdx.x * blockDim.x + threadIdx.x;
    if (idx < W2A_TOT) {
        int t = idx / (3 * 128 * 512);
        int r = idx % (3 * 128 * 512);
        int ct = r / (128 * 512);
        int r2 = r % (128 * 512);
        int n = r2 / 512;
        int k = r2 % 512;
        float w = 0.f;
        if (!(ct == 2 && k >= 256)) {
            int o = k >> 7, kk = k & 127;
            int gate = ct * 2 + ((o >= 2) ? 1 : 0);
            const float* Wsrc = ((o & 1) == 0) ? Wl : Wr;
            int wi = 1 - t;
            w = Wsrc[((size_t)(gate * 2 + wi) * 128 + kk) * 128 + n];
        }
        g_W2A[t][ct][n * 512 + k] = __float2half_rn(w);
        return;
    }
    int i2 = idx - W2A_TOT;
    if (i2 < W2B_TOT) {
        int t = i2 / (128 * 256);
        int r2 = i2 % (128 * 256);
        int n = r2 / 256;
        int k = r2 % 256;
        int o = k >> 7, kk = k & 127;
        const float* Wsrc = (o == 0) ? Wl : Wr;
        int wi = 1 - t;
        float w = Wsrc[((size_t)(5 * 2 + wi) * 128 + kk) * 128 + n];
        g_W2B[t][n * 256 + k] = __float2half_rn(w);
    }
}

__global__ void k_repack2(const float* __restrict__ b) {
    int idx = blockIdx.x * blockDim.x + threadIdx.x;
    if (idx >= 2 * 128) return;
    int t = idx / 128, c = idx % 128;
    int wi = 1 - t;
    g_bias[t][0][c] = b[(0 * 2 + wi) * 128 + c] + b[(1 * 2 + wi) * 128 + c];
    g_bias[t][1][c] = b[(2 * 2 + wi) * 128 + c] + b[(3 * 2 + wi) * 128 + c];
    g_bias[t][2][c] = b[(4 * 2 + wi) * 128 + c];
    g_bias5[t][c]   = b[(5 * 2 + wi) * 128 + c];
}

// ---------------- fp16 tensor-core GEMM (mma.sync) -----------------------------------
__device__ __forceinline__ void load_tile(uint32_t sa, uint32_t sw,
                                          const __half* Ag, const __half* Wg,
                                          int ldw, int tid) {
#pragma unroll
    for (int i = 0; i < 2; i++) {
        int c = tid * 2 + i;
        int row = c >> 2, q = c & 3;
        uint32_t d = sa + (uint32_t)(row * 80 + q * 16);
        const void* s = Ag + (size_t)row * 128 + q * 8;
        asm volatile("cp.async.cg.shared.global [%0], [%1], 16;" :: "r"(d), "l"(s));
        uint32_t d2 = sw + (uint32_t)(row * 80 + q * 16);
        const void* s2 = Wg + (size_t)row * ldw + q * 8;
        asm volatile("cp.async.cg.shared.global [%0], [%1], 16;" :: "r"(d2), "l"(s2));
    }
    asm volatile("cp.async.commit_group;");
}

template <int PASS>
__global__ void __launch_bounds__(256, 2) k_mma(const float* __restrict__ hu,
                                                const float* __restrict__ hn,
                                                float* __restrict__ out) {
    __shared__ __align__(16) unsigned char sA[2][128 * 80];
    __shared__ __align__(16) unsigned char sW[2][128 * 80];
    const int typ = blockIdx.z, ct = blockIdx.y, tm = blockIdx.x;
    const int tid = threadIdx.x, wid = tid >> 5, lane = tid & 31;
    const int wm = wid & 1, wn = wid >> 1;

    const int NO   = (PASS == 0) ? ((ct < 2) ? 4 : 2) : 2;
    const int NIT  = NO * 4;
    const int ldw  = (PASS == 0) ? 512 : 256;
    const __half* Wrow = (PASS == 0) ? g_W2A[typ][ct] : g_W2B[typ];

    uint32_t sAu[2] = { smem_u32(sA[0]), smem_u32(sA[1]) };
    uint32_t sWu[2] = { smem_u32(sW[0]), smem_u32(sW[1]) };

    float acc[4][4][4];
#pragma unroll
    for (int a = 0; a < 4; a++)
#pragma unroll
        for (int bq = 0; bq < 4; bq++)
#pragma unroll
            for (int cq = 0; cq < 4; cq++) acc[a][bq][cq] = 0.f;

    auto asegp = [&](int s) -> const __half* {
        return (PASS == 0) ? &g_Abf[typ][s][0] : &g_Bbf[typ][s][0];
    };

    {
        const __half* Ag = asegp(0) + (size_t)(tm * 128) * 128;
        load_tile(sAu[0], sWu[0], Ag, Wrow, ldw, tid);
    }

#pragma unroll 1
    for (int kt = 0; kt < NIT; kt++) {
        int bsel = kt & 1;
        if (kt + 1 < NIT) {
            int s = (kt + 1) >> 2, kk = ((kt + 1) & 3) * 32;
            const __half* Ag = asegp(s) + (size_t)(tm * 128) * 128 + kk;
            const __half* Wg = Wrow + s * 128 + kk;
            load_tile(sAu[bsel ^ 1], sWu[bsel ^ 1], Ag, Wg, ldw, tid);
            asm volatile("cp.async.wait_group 1;");
        } else {
            asm volatile("cp.async.wait_group 0;");
        }
        __syncthreads();

        uint32_t aB = sAu[bsel] + (uint32_t)((wm * 64) * 80);
        uint32_t bB = sWu[bsel] + (uint32_t)((wn * 32) * 80);
#pragma unroll
        for (int k16 = 0; k16 < 2; k16++) {
            uint32_t afr[4][4], bfr[2][4];
#pragma unroll
            for (int mt = 0; mt < 4; mt++) {
                uint32_t addr = aB + (uint32_t)((mt * 16 + (lane & 15)) * 80 +
                                                k16 * 32 + (lane >> 4) * 16);
                ldsm4(afr[mt], addr);
            }
#pragma unroll
            for (int np = 0; np < 2; np++) {
                uint32_t addr = bB + (uint32_t)((np * 16 + (lane & 7) + ((lane >> 4) * 8)) * 80 +
                                                k16 * 32 + ((lane >> 3) & 1) * 16);
                ldsm4(bfr[np], addr);
            }
#pragma unroll
            for (int mt = 0; mt < 4; mt++)
#pragma unroll
                for (int nt = 0; nt < 4; nt++)
                    mma16816(acc[mt][nt], afr[mt],
                             bfr[nt >> 1][(nt & 1) * 2], bfr[nt >> 1][(nt & 1) * 2 + 1]);
        }
        __syncthreads();
    }

    // ---------------- epilogue ----------------
    const float* hself = typ ? hn : hu;
    int rowW = tm * 128 + wm * 64;
    int colW = wn * 32;
#pragma unroll
    for (int mt = 0; mt < 4; mt++) {
#pragma unroll
        for (int i = 0; i < 2; i++) {
            int row = rowW + mt * 16 + (lane >> 2) + i * 8;
            if (row >= N_NODES) continue;
#pragma unroll
            for (int nt = 0; nt < 4; nt++) {
                int col = colW + nt * 8 + (lane & 3) * 2;
                size_t off = (size_t)row * DIM + col;
                float v0, v1;
                if (PASS == 0) {
                    const float* bias = g_bias[typ][ct];
                    v0 = acc[mt][nt][i * 2 + 0] + bias[col];
                    v1 = acc[mt][nt][i * 2 + 1] + bias[col + 1];
                    if (ct == 0) {
                        *(float2*)&g_z[typ][off] = make_float2(sigmoidf_(v0), sigmoidf_(v1));
                    } else if (ct == 1) {
                        float2 h2 = *(const float2*)&hself[off];
                        float hr0 = h2.x * sigmoidf_(v0);
                        float hr1 = h2.y * sigmoidf_(v1);
                        *(uint32_t*)&g_Bbf[typ][1][off] = packh2(hr0, hr1);
                    } else {
                        *(float2*)&g_cx[typ][off] = make_float2(v0, v1);
                    }
                } else {
                    const float* bias = g_bias5[typ];
                    v0 = acc[mt][nt][i * 2 + 0] + bias[col];
                    v1 = acc[mt][nt][i * 2 + 1] + bias[col + 1];
                    float2 cx2 = *(const float2*)&g_cx[typ][off];
                    float2 z2  = *(const float2*)&g_z[typ][off];
                    float2 h2  = *(const float2*)&hself[off];
                    float ht0 = tanhf(cx2.x + v0);
                    float ht1 = tanhf(cx2.y + v1);
                    float2 o2;
                    o2.x = z2.x * h2.x + (1.f - z2.x) * ht0;
                    o2.y = z2.y * h2.y + (1.f - z2.y) * ht1;
                    *(float2*)&out[(size_t)typ * N_NODES * DIM + off] = o2;
                }
            }
        }
    }
}

// ---------------- launch ----------------------------------------------------------------
extern "C" void kernel_launch(void* const* d_in, const int* in_sizes, int n_in,
                              void* d_out, int out_size) {
    const float* x_user = (const float*)d_in[0];
    const float* x_news = (const float*)d_in[1];
    const float* h_user = (const float*)d_in[2];
    const float* h_news = (const float*)d_in[3];
    const float* Wl     = (const float*)d_in[4];
    const float* Wr     = (const float*)d_in[5];
    const float* b      = (const float*)d_in[6];
    const int* src_un   = (const int*)d_in[7];
    const int* dst_un   = (const int*)d_in[8];
    const int* src_nu   = (const int*)d_in[9];
    const int* dst_nu   = (const int*)d_in[10];
    float* out = (float*)d_out;
    const int E = in_sizes[7];

    // CSR build
    k_zero2<<<(N_NODES + 255) / 256, 256>>>();
    k_deg2<<<(E + 255) / 256, 256>>>(dst_un, dst_nu, E);
    k_scan<<<2, 1024>>>();
    k_fill<<<(E + 255) / 256, 256>>>(src_un, dst_un, src_nu, dst_nu, E);

    // weight/bias prep + self-feature conversion
    k_repackW<<<(W2A_TOT + W2B_TOT + 255) / 256, 256>>>(Wl, Wr);
    k_repack2<<<1, 256>>>(b);
    k_conv_xh<<<(2 * 2 * MPAD * 16 + 255) / 256, 256>>>(x_user, h_user, x_news, h_news);

    // aggregation from fp16 tables (gather, fused mean + fp16 store)
    int ablocks = (MPAD * 32 + 255) / 256;
    k_agg_xh<0><<<ablocks, 256>>>();   // user dst <- news fp16 x/h
    k_agg_xh<1><<<ablocks, 256>>>();   // news dst <- user fp16 x/h

    dim3 gA(NTM, 3, 2);
    k_mma<0><<<gA, 256>>>(h_user, h_news, out);

    k_agg_hr<0><<<ablocks, 256>>>();
    k_agg_hr<1><<<ablocks, 256>>>();

    dim3 gB(NTM, 1, 2);
    k_mma<1><<<gB, 256>>>(h_user, h_news, out);
}